// round 3
// baseline (speedup 1.0000x reference)
#include <cuda_runtime.h>
#include <math.h>

#define NMAX 100000
#define EMAX 3200000
#define ETMAX (EMAX + NMAX)

// ---------- scratch (static __device__ arrays; no allocation allowed) ----------
__device__ __align__(16) int   d_src[ETMAX];
__device__ __align__(16) int   d_dst[ETMAX];

__device__ __align__(16) float d_h1 [NMAX * 32];
__device__ __align__(16) float d_as1[NMAX * 4];
__device__ __align__(16) float d_ad1[NMAX * 4];
__device__ __align__(16) unsigned int d_m1[NMAX * 4];
__device__ __align__(16) float d_s1 [NMAX * 4];
__device__ __align__(16) float d_out1[NMAX * 32];
__device__ __align__(16) float d_alpha1[ETMAX * 4];

__device__ __align__(16) float d_g  [NMAX * 2];
__device__ __align__(16) float d_as2[NMAX];
__device__ __align__(16) float d_ad2[NMAX];
__device__ __align__(16) unsigned int d_m2[NMAX];
__device__ __align__(16) float d_s2 [NMAX];
__device__ __align__(16) float d_out2[NMAX * 2];
__device__ __align__(16) float d_alpha2[ETMAX];

// ---------- monotone float<->uint key for atomicMax on floats ----------
__device__ __forceinline__ unsigned int fkey(float f) {
    unsigned int b = __float_as_uint(f);
    return (b & 0x80000000u) ? ~b : (b | 0x80000000u);
}
__device__ __forceinline__ float funkey(unsigned int u) {
    unsigned int b = (u & 0x80000000u) ? (u ^ 0x80000000u) : ~u;
    return __uint_as_float(b);
}

__device__ __forceinline__ float lrelu(float v) { return v > 0.0f ? v : 0.2f * v; }

// ---------- edge index prep: int32 [2,E] + self loops -> src/dst ----------
// NOTE: harness stores edge_index as int32 (int64 is not in its dtype set).
__global__ void k_prep_edges(const int* __restrict__ ei, int E, int ET) {
    int i = blockIdx.x * blockDim.x + threadIdx.x;
    if (i >= ET) return;
    if (i < E) {
        d_src[i] = ei[i];
        d_dst[i] = ei[E + i];
    } else {
        d_src[i] = i - E;
        d_dst[i] = i - E;
    }
}

// ---------- layer 1: node transform + init ----------
__global__ void k_node1(const float* __restrict__ x, const float* __restrict__ W1,
                        const float* __restrict__ asr, const float* __restrict__ adr, int N) {
    int n = blockIdx.x * blockDim.x + threadIdx.x;
    if (n >= N) return;
    float x0 = x[2 * n], x1 = x[2 * n + 1];
    float h[32];
#pragma unroll
    for (int k = 0; k < 32; k++) h[k] = x0 * W1[k] + x1 * W1[32 + k];
#pragma unroll
    for (int hh = 0; hh < 4; hh++) {
        float s = 0.f, d = 0.f;
#pragma unroll
        for (int c = 0; c < 8; c++) {
            s += h[hh * 8 + c] * asr[hh * 8 + c];
            d += h[hh * 8 + c] * adr[hh * 8 + c];
        }
        d_as1[n * 4 + hh] = s;
        d_ad1[n * 4 + hh] = d;
        d_m1[n * 4 + hh]  = fkey(-3.4e38f);
        d_s1[n * 4 + hh]  = 0.f;
    }
#pragma unroll
    for (int k = 0; k < 32; k++) { d_h1[n * 32 + k] = h[k]; d_out1[n * 32 + k] = 0.f; }
}

// ---------- layer 1: edge pass A (e = lrelu, segment max) ----------
__global__ void k_edge1a(int ET) {
    int i = blockIdx.x * blockDim.x + threadIdx.x;
    if (i >= ET) return;
    int s = d_src[i], d = d_dst[i];
    float4 as = *(const float4*)&d_as1[s * 4];
    float4 ad = *(const float4*)&d_ad1[d * 4];
    float e0 = lrelu(as.x + ad.x), e1 = lrelu(as.y + ad.y);
    float e2 = lrelu(as.z + ad.z), e3 = lrelu(as.w + ad.w);
    atomicMax(&d_m1[d * 4 + 0], fkey(e0));
    atomicMax(&d_m1[d * 4 + 1], fkey(e1));
    atomicMax(&d_m1[d * 4 + 2], fkey(e2));
    atomicMax(&d_m1[d * 4 + 3], fkey(e3));
    *(float4*)&d_alpha1[i * 4] = make_float4(e0, e1, e2, e3);
}

// ---------- layer 1: edge pass B (exp + segment sum) ----------
__global__ void k_edge1b(int ET) {
    int i = blockIdx.x * blockDim.x + threadIdx.x;
    if (i >= ET) return;
    int d = d_dst[i];
    float4 e = *(const float4*)&d_alpha1[i * 4];
    uint4 mk = *(const uint4*)&d_m1[d * 4];
    float4 ee;
    ee.x = __expf(e.x - funkey(mk.x));
    ee.y = __expf(e.y - funkey(mk.y));
    ee.z = __expf(e.z - funkey(mk.z));
    ee.w = __expf(e.w - funkey(mk.w));
    *(float4*)&d_alpha1[i * 4] = ee;
    atomicAdd((float4*)&d_s1[d * 4], ee);
}

// ---------- layer 1: edge pass C (normalize + aggregate) ----------
__global__ void k_edge1c(int ET) {
    int i = blockIdx.x * blockDim.x + threadIdx.x;
    if (i >= ET) return;
    int s = d_src[i], d = d_dst[i];
    float4 ee = *(const float4*)&d_alpha1[i * 4];
    float4 sm = *(const float4*)&d_s1[d * 4];
    float a[4];
    a[0] = ee.x / (sm.x + 1e-16f);
    a[1] = ee.y / (sm.y + 1e-16f);
    a[2] = ee.z / (sm.z + 1e-16f);
    a[3] = ee.w / (sm.w + 1e-16f);
    *(float4*)&d_alpha1[i * 4] = make_float4(a[0], a[1], a[2], a[3]);
    const float4* hs = (const float4*)&d_h1[s * 32];
    float4* od = (float4*)&d_out1[d * 32];
#pragma unroll
    for (int h = 0; h < 4; h++) {
        float4 v0 = hs[h * 2], v1 = hs[h * 2 + 1];
        float al = a[h];
        atomicAdd(&od[h * 2],     make_float4(v0.x * al, v0.y * al, v0.z * al, v0.w * al));
        atomicAdd(&od[h * 2 + 1], make_float4(v1.x * al, v1.y * al, v1.z * al, v1.w * al));
    }
}

// ---------- layer 2: node transform (elu + GEMV) + init ----------
__global__ void k_node2(const float* __restrict__ b1, const float* __restrict__ W2,
                        const float* __restrict__ asr, const float* __restrict__ adr, int N) {
    int n = blockIdx.x * blockDim.x + threadIdx.x;
    if (n >= N) return;
    float g0 = 0.f, g1 = 0.f;
#pragma unroll
    for (int k = 0; k < 32; k++) {
        float v = d_out1[n * 32 + k] + b1[k];
        v = v > 0.f ? v : expm1f(v);
        g0 += v * W2[k * 2];
        g1 += v * W2[k * 2 + 1];
    }
    d_g[n * 2]     = g0;
    d_g[n * 2 + 1] = g1;
    d_as2[n] = g0 * asr[0] + g1 * asr[1];
    d_ad2[n] = g0 * adr[0] + g1 * adr[1];
    d_m2[n]  = fkey(-3.4e38f);
    d_s2[n]  = 0.f;
    d_out2[n * 2] = 0.f;
    d_out2[n * 2 + 1] = 0.f;
}

// ---------- layer 2: edge passes ----------
__global__ void k_edge2a(int ET) {
    int i = blockIdx.x * blockDim.x + threadIdx.x;
    if (i >= ET) return;
    int s = d_src[i], d = d_dst[i];
    float e = lrelu(d_as2[s] + d_ad2[d]);
    atomicMax(&d_m2[d], fkey(e));
    d_alpha2[i] = e;
}
__global__ void k_edge2b(int ET) {
    int i = blockIdx.x * blockDim.x + threadIdx.x;
    if (i >= ET) return;
    int d = d_dst[i];
    float ee = __expf(d_alpha2[i] - funkey(d_m2[d]));
    d_alpha2[i] = ee;
    atomicAdd(&d_s2[d], ee);
}
__global__ void k_edge2c(int ET) {
    int i = blockIdx.x * blockDim.x + threadIdx.x;
    if (i >= ET) return;
    int s = d_src[i], d = d_dst[i];
    float al = d_alpha2[i] / (d_s2[d] + 1e-16f);
    d_alpha2[i] = al;
    float2 g = *(const float2*)&d_g[s * 2];
    atomicAdd((float2*)&d_out2[d * 2], make_float2(g.x * al, g.y * al));
}

// ---------- finalize: out = out2 + b2 ; copy alphas into d_out if room ----------
__global__ void k_finalize(float* __restrict__ out, const float* __restrict__ b2,
                           int N, int ET, int out_size) {
    int i = blockIdx.x * blockDim.x + threadIdx.x;
    if (i >= out_size) return;
    int total = N * 2 + ET * 4 + ET;
    if (i < N * 2) {
        out[i] = d_out2[i] + b2[i & 1];
    } else if (out_size >= total) {
        if (i < N * 2 + ET * 4) out[i] = d_alpha1[i - N * 2];
        else if (i < total)     out[i] = d_alpha2[i - N * 2 - ET * 4];
        else                    out[i] = 0.f;
    } else {
        out[i] = 0.f;  // unknown extra region: deterministic fill
    }
}

extern "C" void kernel_launch(void* const* d_in, const int* in_sizes, int n_in,
                              void* d_out, int out_size) {
    const float* x   = (const float*)d_in[0];
    const int*   ei  = (const int*)d_in[1];   // edge_index stored as int32 by harness
    // d_in[2] = edge_attr (ignored by reference)
    const float* W1   = (const float*)d_in[3];
    const float* as1  = (const float*)d_in[4];
    const float* ad1  = (const float*)d_in[5];
    const float* b1   = (const float*)d_in[6];
    const float* W2   = (const float*)d_in[7];
    const float* as2  = (const float*)d_in[8];
    const float* ad2  = (const float*)d_in[9];
    const float* b2   = (const float*)d_in[10];
    float* out = (float*)d_out;

    int N  = in_sizes[0] / 2;
    int E  = in_sizes[1] / 2;
    int ET = E + N;

    const int T = 256;
    int gN  = (N  + T - 1) / T;
    int gET = (ET + T - 1) / T;
    int gO  = (out_size + T - 1) / T;

    k_prep_edges<<<gET, T>>>(ei, E, ET);
    k_node1<<<gN, T>>>(x, W1, as1, ad1, N);
    k_edge1a<<<gET, T>>>(ET);
    k_edge1b<<<gET, T>>>(ET);
    k_edge1c<<<gET, T>>>(ET);
    k_node2<<<gN, T>>>(b1, W2, as2, ad2, N);
    k_edge2a<<<gET, T>>>(ET);
    k_edge2b<<<gET, T>>>(ET);
    k_edge2c<<<gET, T>>>(ET);
    k_finalize<<<gO, T>>>(out, b2, N, ET, out_size);
}

// round 4
// speedup vs baseline: 1.1697x; 1.1697x over previous
#include <cuda_runtime.h>
#include <math.h>

#define NMAX 100000
#define EMAX 3200000
#define ETMAX (EMAX + NMAX)

// ---------- scratch (static __device__ arrays; no allocation allowed) ----------
__device__ __align__(16) int   d_src[ETMAX];
__device__ __align__(16) int   d_dst[ETMAX];

__device__ __align__(16) float d_h1 [NMAX * 32];
__device__ __align__(16) float d_as1[NMAX * 4];
__device__ __align__(16) float d_ad1[NMAX * 4];
__device__ __align__(16) float d_s1 [NMAX * 4];
__device__ __align__(16) float d_out1[NMAX * 32];

__device__ __align__(16) float d_g  [NMAX * 2];
__device__ __align__(16) float d_as2[NMAX];
__device__ __align__(16) float d_ad2[NMAX];
__device__ __align__(16) float d_s2 [NMAX];
__device__ __align__(16) float d_out2[NMAX * 2];

__device__ __forceinline__ float lrelu(float v) { return v > 0.0f ? v : 0.2f * v; }

// ---------- edge index prep: int32 [2,E] + self loops -> src/dst ----------
__global__ void k_prep_edges(const int* __restrict__ ei, int E, int ET) {
    int i = blockIdx.x * blockDim.x + threadIdx.x;
    if (i >= ET) return;
    if (i < E) {
        d_src[i] = ei[i];
        d_dst[i] = ei[E + i];
    } else {
        d_src[i] = i - E;
        d_dst[i] = i - E;
    }
}

// ---------- layer 1: node transform + init ----------
__global__ void k_node1(const float* __restrict__ x, const float* __restrict__ W1,
                        const float* __restrict__ asr, const float* __restrict__ adr, int N) {
    int n = blockIdx.x * blockDim.x + threadIdx.x;
    if (n >= N) return;
    float x0 = x[2 * n], x1 = x[2 * n + 1];
    float h[32];
#pragma unroll
    for (int k = 0; k < 32; k++) h[k] = x0 * W1[k] + x1 * W1[32 + k];
#pragma unroll
    for (int hh = 0; hh < 4; hh++) {
        float s = 0.f, d = 0.f;
#pragma unroll
        for (int c = 0; c < 8; c++) {
            s += h[hh * 8 + c] * asr[hh * 8 + c];
            d += h[hh * 8 + c] * adr[hh * 8 + c];
        }
        d_as1[n * 4 + hh] = s;
        d_ad1[n * 4 + hh] = d;
        d_s1[n * 4 + hh]  = 0.f;
    }
#pragma unroll
    for (int k = 0; k < 32; k++) { d_h1[n * 32 + k] = h[k]; d_out1[n * 32 + k] = 0.f; }
}

// exp(e) recomputed identically in sum+agg passes -> deterministic, no scratch.
__device__ __forceinline__ float4 edge1_ee(int s, int d) {
    float4 as = *(const float4*)&d_as1[s * 4];
    float4 ad = *(const float4*)&d_ad1[d * 4];
    float4 ee;
    ee.x = __expf(lrelu(as.x + ad.x));
    ee.y = __expf(lrelu(as.y + ad.y));
    ee.z = __expf(lrelu(as.z + ad.z));
    ee.w = __expf(lrelu(as.w + ad.w));
    return ee;
}

// ---------- layer 1: pass 1 (exp + segment sum) ----------
__global__ void k_edge1_sum(int ET) {
    int i = blockIdx.x * blockDim.x + threadIdx.x;
    if (i >= ET) return;
    int d = d_dst[i];
    float4 ee = edge1_ee(d_src[i], d);
    atomicAdd((float4*)&d_s1[d * 4], ee);
}

// ---------- layer 1: pass 2 (normalize + aggregate + emit alpha to out) ----------
__global__ void k_edge1_agg(float* __restrict__ alpha_out, int ET) {
    int i = blockIdx.x * blockDim.x + threadIdx.x;
    if (i >= ET) return;
    int s = d_src[i], d = d_dst[i];
    float4 ee = edge1_ee(s, d);
    float4 sm = *(const float4*)&d_s1[d * 4];
    float a0 = ee.x / (sm.x + 1e-16f);
    float a1 = ee.y / (sm.y + 1e-16f);
    float a2 = ee.z / (sm.z + 1e-16f);
    float a3 = ee.w / (sm.w + 1e-16f);
    if (alpha_out) *(float4*)&alpha_out[i * 4] = make_float4(a0, a1, a2, a3);
    const float4* hs = (const float4*)&d_h1[s * 32];
    float4* od = (float4*)&d_out1[d * 32];
    float a[4] = {a0, a1, a2, a3};
#pragma unroll
    for (int h = 0; h < 4; h++) {
        float4 v0 = hs[h * 2], v1 = hs[h * 2 + 1];
        float al = a[h];
        atomicAdd(&od[h * 2],     make_float4(v0.x * al, v0.y * al, v0.z * al, v0.w * al));
        atomicAdd(&od[h * 2 + 1], make_float4(v1.x * al, v1.y * al, v1.z * al, v1.w * al));
    }
}

// ---------- layer 2: node transform (elu + GEMV) + init ----------
__global__ void k_node2(const float* __restrict__ b1, const float* __restrict__ W2,
                        const float* __restrict__ asr, const float* __restrict__ adr, int N) {
    int n = blockIdx.x * blockDim.x + threadIdx.x;
    if (n >= N) return;
    float g0 = 0.f, g1 = 0.f;
#pragma unroll
    for (int k = 0; k < 32; k++) {
        float v = d_out1[n * 32 + k] + b1[k];
        v = v > 0.f ? v : expm1f(v);
        g0 += v * W2[k * 2];
        g1 += v * W2[k * 2 + 1];
    }
    d_g[n * 2]     = g0;
    d_g[n * 2 + 1] = g1;
    d_as2[n] = g0 * asr[0] + g1 * asr[1];
    d_ad2[n] = g0 * adr[0] + g1 * adr[1];
    d_s2[n]  = 0.f;
    d_out2[n * 2] = 0.f;
    d_out2[n * 2 + 1] = 0.f;
}

// ---------- layer 2: edge passes ----------
__global__ void k_edge2_sum(int ET) {
    int i = blockIdx.x * blockDim.x + threadIdx.x;
    if (i >= ET) return;
    int d = d_dst[i];
    float ee = __expf(lrelu(d_as2[d_src[i]] + d_ad2[d]));
    atomicAdd(&d_s2[d], ee);
}
__global__ void k_edge2_agg(float* __restrict__ alpha_out, int ET) {
    int i = blockIdx.x * blockDim.x + threadIdx.x;
    if (i >= ET) return;
    int s = d_src[i], d = d_dst[i];
    float ee = __expf(lrelu(d_as2[s] + d_ad2[d]));
    float al = ee / (d_s2[d] + 1e-16f);
    if (alpha_out) alpha_out[i] = al;
    float2 g = *(const float2*)&d_g[s * 2];
    atomicAdd((float2*)&d_out2[d * 2], make_float2(g.x * al, g.y * al));
}

// ---------- finalize: out[0..2N) = out2 + b2 ; zero tail past alpha regions ----------
__global__ void k_finalize(float* __restrict__ out, const float* __restrict__ b2,
                           int N, int ET, int out_size) {
    int i = blockIdx.x * blockDim.x + threadIdx.x;
    if (i >= out_size) return;
    int total = N * 2 + ET * 4 + ET;
    if (i < N * 2) {
        out[i] = d_out2[i] + b2[i & 1];
    } else if (out_size >= total) {
        if (i >= total) out[i] = 0.f;   // tail beyond known layout
        // [2N, total): written by edge agg kernels (alpha1, alpha2)
    } else {
        out[i] = 0.f;                   // unknown smaller layout: deterministic fill
    }
}

extern "C" void kernel_launch(void* const* d_in, const int* in_sizes, int n_in,
                              void* d_out, int out_size) {
    const float* x   = (const float*)d_in[0];
    const int*   ei  = (const int*)d_in[1];   // edge_index stored as int32 by harness
    // d_in[2] = edge_attr (ignored by reference)
    const float* W1   = (const float*)d_in[3];
    const float* as1  = (const float*)d_in[4];
    const float* ad1  = (const float*)d_in[5];
    const float* b1   = (const float*)d_in[6];
    const float* W2   = (const float*)d_in[7];
    const float* as2  = (const float*)d_in[8];
    const float* ad2  = (const float*)d_in[9];
    const float* b2   = (const float*)d_in[10];
    float* out = (float*)d_out;

    int N  = in_sizes[0] / 2;
    int E  = in_sizes[1] / 2;
    int ET = E + N;
    long long total = (long long)N * 2 + (long long)ET * 5;

    // alpha destinations inside d_out (only if the full layout fits)
    float* alpha1_out = (out_size >= total) ? out + (size_t)N * 2 : nullptr;
    float* alpha2_out = (out_size >= total) ? out + (size_t)N * 2 + (size_t)ET * 4 : nullptr;

    const int T = 256;
    int gN  = (N  + T - 1) / T;
    int gET = (ET + T - 1) / T;
    int gO  = (out_size + T - 1) / T;

    k_prep_edges<<<gET, T>>>(ei, E, ET);
    k_node1<<<gN, T>>>(x, W1, as1, ad1, N);
    k_edge1_sum<<<gET, T>>>(ET);
    k_edge1_agg<<<gET, T>>>(alpha1_out, ET);
    k_node2<<<gN, T>>>(b1, W2, as2, ad2, N);
    k_edge2_sum<<<gET, T>>>(ET);
    k_edge2_agg<<<gET, T>>>(alpha2_out, ET);
    k_finalize<<<gO, T>>>(out, b2, N, ET, out_size);
}

// round 5
// speedup vs baseline: 1.5476x; 1.3231x over previous
#include <cuda_runtime.h>
#include <math.h>

#define NMAX 100000
#define EMAX 3200000
#define ETMAX (EMAX + NMAX)

// ---------- scratch (static __device__ arrays; no allocation allowed) ----------
__device__ __align__(16) int   d_src[ETMAX];
__device__ __align__(16) int   d_dst[ETMAX];

__device__ __align__(16) float d_h1 [NMAX * 32];
__device__ __align__(16) float d_as1[NMAX * 4];
__device__ __align__(16) float d_ad1[NMAX * 4];
__device__ __align__(16) float d_s1 [NMAX * 4];
__device__ __align__(16) float d_out1[NMAX * 32];

__device__ __align__(16) float d_g  [NMAX * 2];
__device__ __align__(16) float d_as2[NMAX];
__device__ __align__(16) float d_ad2[NMAX];
__device__ __align__(16) float d_s2 [NMAX];
__device__ __align__(16) float d_out2[NMAX * 2];

__device__ __forceinline__ float lrelu(float v) { return v > 0.0f ? v : 0.2f * v; }

// ---------- edge index prep: int32 [2,E] + self loops -> src/dst ----------
__global__ void k_prep_edges(const int* __restrict__ ei, int E, int ET) {
    int i = blockIdx.x * blockDim.x + threadIdx.x;
    if (i >= ET) return;
    if (i < E) {
        d_src[i] = ei[i];
        d_dst[i] = ei[E + i];
    } else {
        d_src[i] = i - E;
        d_dst[i] = i - E;
    }
}

// ---------- layer 1: node transform + init ----------
__global__ void k_node1(const float* __restrict__ x, const float* __restrict__ W1,
                        const float* __restrict__ asr, const float* __restrict__ adr, int N) {
    int n = blockIdx.x * blockDim.x + threadIdx.x;
    if (n >= N) return;
    float x0 = x[2 * n], x1 = x[2 * n + 1];
    float h[32];
#pragma unroll
    for (int k = 0; k < 32; k++) h[k] = x0 * W1[k] + x1 * W1[32 + k];
#pragma unroll
    for (int hh = 0; hh < 4; hh++) {
        float s = 0.f, d = 0.f;
#pragma unroll
        for (int c = 0; c < 8; c++) {
            s += h[hh * 8 + c] * asr[hh * 8 + c];
            d += h[hh * 8 + c] * adr[hh * 8 + c];
        }
        d_as1[n * 4 + hh] = s;
        d_ad1[n * 4 + hh] = d;
        d_s1[n * 4 + hh]  = 0.f;
    }
#pragma unroll
    for (int k = 0; k < 32; k++) { d_h1[n * 32 + k] = h[k]; d_out1[n * 32 + k] = 0.f; }
}

// exp(e) recomputed identically in sum+agg passes -> deterministic, no scratch.
__device__ __forceinline__ float4 edge1_ee4(int s, int d) {
    float4 as = *(const float4*)&d_as1[s * 4];
    float4 ad = *(const float4*)&d_ad1[d * 4];
    float4 ee;
    ee.x = __expf(lrelu(as.x + ad.x));
    ee.y = __expf(lrelu(as.y + ad.y));
    ee.z = __expf(lrelu(as.z + ad.z));
    ee.w = __expf(lrelu(as.w + ad.w));
    return ee;
}

// ---------- layer 1: pass 1 (exp + segment sum) ----------
__global__ void k_edge1_sum(int ET) {
    int i = blockIdx.x * blockDim.x + threadIdx.x;
    if (i >= ET) return;
    int d = d_dst[i];
    float4 ee = edge1_ee4(d_src[i], d);
    atomicAdd((float4*)&d_s1[d * 4], ee);
}

// ---------- layer 1: pass 2 (normalize + aggregate + emit alpha) ----------
// 8 threads per edge: thread j owns float4 chunk j of the 128-byte h1/out1 row.
// One LDG.128 / RED.128 per warp now spans 4 whole edges -> 4 wavefronts
// instead of 32 (coalesced gather/scatter).
__global__ void k_edge1_agg(float* __restrict__ alpha_out, int ET) {
    int t = blockIdx.x * blockDim.x + threadIdx.x;
    int i = t >> 3;
    if (i >= ET) return;
    int j = t & 7;          // chunk 0..7
    int h = j >> 1;         // head 0..3 (2 chunks per head)
    int s = d_src[i], d = d_dst[i];

    float as = d_as1[s * 4 + h];
    float ad = d_ad1[d * 4 + h];
    float ee = __expf(lrelu(as + ad));
    float sm = d_s1[d * 4 + h];
    float al = ee / (sm + 1e-16f);

    if (alpha_out && (j & 1) == 0) alpha_out[i * 4 + h] = al;

    float4 v = ((const float4*)&d_h1[s * 32])[j];
    atomicAdd(&((float4*)&d_out1[d * 32])[j],
              make_float4(v.x * al, v.y * al, v.z * al, v.w * al));
}

// ---------- layer 2: node transform (elu + GEMV) + init ----------
__global__ void k_node2(const float* __restrict__ b1, const float* __restrict__ W2,
                        const float* __restrict__ asr, const float* __restrict__ adr, int N) {
    int n = blockIdx.x * blockDim.x + threadIdx.x;
    if (n >= N) return;
    float g0 = 0.f, g1 = 0.f;
#pragma unroll
    for (int k = 0; k < 32; k++) {
        float v = d_out1[n * 32 + k] + b1[k];
        v = v > 0.f ? v : expm1f(v);
        g0 += v * W2[k * 2];
        g1 += v * W2[k * 2 + 1];
    }
    d_g[n * 2]     = g0;
    d_g[n * 2 + 1] = g1;
    d_as2[n] = g0 * asr[0] + g1 * asr[1];
    d_ad2[n] = g0 * adr[0] + g1 * adr[1];
    d_s2[n]  = 0.f;
    d_out2[n * 2] = 0.f;
    d_out2[n * 2 + 1] = 0.f;
}

// ---------- layer 2: edge passes ----------
__global__ void k_edge2_sum(int ET) {
    int i = blockIdx.x * blockDim.x + threadIdx.x;
    if (i >= ET) return;
    int d = d_dst[i];
    float ee = __expf(lrelu(d_as2[d_src[i]] + d_ad2[d]));
    atomicAdd(&d_s2[d], ee);
}
__global__ void k_edge2_agg(float* __restrict__ alpha_out, int ET) {
    int i = blockIdx.x * blockDim.x + threadIdx.x;
    if (i >= ET) return;
    int s = d_src[i], d = d_dst[i];
    float ee = __expf(lrelu(d_as2[s] + d_ad2[d]));
    float al = ee / (d_s2[d] + 1e-16f);
    if (alpha_out) alpha_out[i] = al;
    float2 g = *(const float2*)&d_g[s * 2];
    atomicAdd((float2*)&d_out2[d * 2], make_float2(g.x * al, g.y * al));
}

// ---------- finalize: out[0..2N) = out2 + b2 ; zero tail past alpha regions ----------
__global__ void k_finalize(float* __restrict__ out, const float* __restrict__ b2,
                           int N, int ET, int out_size) {
    int i = blockIdx.x * blockDim.x + threadIdx.x;
    if (i >= out_size) return;
    int total = N * 2 + ET * 4 + ET;
    if (i < N * 2) {
        out[i] = d_out2[i] + b2[i & 1];
    } else if (out_size >= total) {
        if (i >= total) out[i] = 0.f;   // tail beyond known layout
        // [2N, total): written by edge agg kernels (alpha1, alpha2)
    } else {
        out[i] = 0.f;                   // unknown smaller layout: deterministic fill
    }
}

extern "C" void kernel_launch(void* const* d_in, const int* in_sizes, int n_in,
                              void* d_out, int out_size) {
    const float* x   = (const float*)d_in[0];
    const int*   ei  = (const int*)d_in[1];   // edge_index stored as int32 by harness
    // d_in[2] = edge_attr (ignored by reference)
    const float* W1   = (const float*)d_in[3];
    const float* as1  = (const float*)d_in[4];
    const float* ad1  = (const float*)d_in[5];
    const float* b1   = (const float*)d_in[6];
    const float* W2   = (const float*)d_in[7];
    const float* as2  = (const float*)d_in[8];
    const float* ad2  = (const float*)d_in[9];
    const float* b2   = (const float*)d_in[10];
    float* out = (float*)d_out;

    int N  = in_sizes[0] / 2;
    int E  = in_sizes[1] / 2;
    int ET = E + N;
    long long total = (long long)N * 2 + (long long)ET * 5;

    float* alpha1_out = (out_size >= total) ? out + (size_t)N * 2 : nullptr;
    float* alpha2_out = (out_size >= total) ? out + (size_t)N * 2 + (size_t)ET * 4 : nullptr;

    const int T = 256;
    int gN   = (N  + T - 1) / T;
    int gET  = (ET + T - 1) / T;
    int gET8 = (ET * 8 + T - 1) / T;   // 8 threads per edge
    int gO   = (out_size + T - 1) / T;

    k_prep_edges<<<gET, T>>>(ei, E, ET);
    k_node1<<<gN, T>>>(x, W1, as1, ad1, N);
    k_edge1_sum<<<gET, T>>>(ET);
    k_edge1_agg<<<gET8, T>>>(alpha1_out, ET);
    k_node2<<<gN, T>>>(b1, W2, as2, ad2, N);
    k_edge2_sum<<<gET, T>>>(ET);
    k_edge2_agg<<<gET, T>>>(alpha2_out, ET);
    k_finalize<<<gO, T>>>(out, b2, N, ET, out_size);
}

// round 6
// speedup vs baseline: 1.7126x; 1.1066x over previous
#include <cuda_runtime.h>
#include <math.h>

#define NMAX 100000
#define EMAX 3200000
#define ETMAX (EMAX + NMAX)

// ---------- scratch (static __device__ arrays; no allocation allowed) ----------
__device__ __align__(16) float d_h1 [NMAX * 32];
__device__ __align__(16) float d_as1[NMAX * 4];
__device__ __align__(16) float d_ad1[NMAX * 4];
__device__ __align__(16) float d_s1 [NMAX * 4];
__device__ __align__(16) float d_out1[NMAX * 32];

__device__ __align__(16) float4 d_p2s[NMAX];   // {g0, g1, as2, unused}
__device__ __align__(16) float2 d_p2d[NMAX];   // {ad2, s2-accumulator}
__device__ __align__(16) float d_out2[NMAX * 2];

__device__ __forceinline__ float lrelu(float v) { return v > 0.0f ? v : 0.2f * v; }

// decode edge i (with self loops appended) directly from the input buffer
__device__ __forceinline__ void edge_sd(const int* __restrict__ ei, int i, int E,
                                        int& s, int& d) {
    if (i < E) { s = ei[i]; d = ei[E + i]; }
    else       { s = i - E; d = i - E; }
}

// ---------- layer 1: node transform + init ----------
__global__ void k_node1(const float* __restrict__ x, const float* __restrict__ W1,
                        const float* __restrict__ asr, const float* __restrict__ adr, int N) {
    int n = blockIdx.x * blockDim.x + threadIdx.x;
    if (n >= N) return;
    float x0 = x[2 * n], x1 = x[2 * n + 1];
    float h[32];
#pragma unroll
    for (int k = 0; k < 32; k++) h[k] = x0 * W1[k] + x1 * W1[32 + k];
#pragma unroll
    for (int hh = 0; hh < 4; hh++) {
        float s = 0.f, d = 0.f;
#pragma unroll
        for (int c = 0; c < 8; c++) {
            s += h[hh * 8 + c] * asr[hh * 8 + c];
            d += h[hh * 8 + c] * adr[hh * 8 + c];
        }
        d_as1[n * 4 + hh] = s;
        d_ad1[n * 4 + hh] = d;
        d_s1[n * 4 + hh]  = 0.f;
    }
#pragma unroll
    for (int k = 0; k < 32; k++) { d_h1[n * 32 + k] = h[k]; d_out1[n * 32 + k] = 0.f; }
}

// ---------- layer 1: pass 1 (exp + segment sum), 4 threads per edge ----------
// 4 lanes of an edge read within one 16B span of as1/ad1/s1 -> distinct-line
// count per warp drops 32 -> 8 per memory instruction.
__global__ void k_edge1_sum(const int* __restrict__ ei, int E, int ET) {
    int t = blockIdx.x * blockDim.x + threadIdx.x;
    int i = t >> 2;
    if (i >= ET) return;
    int h = t & 3;
    int s, d; edge_sd(ei, i, E, s, d);
    float ee = __expf(lrelu(d_as1[s * 4 + h] + d_ad1[d * 4 + h]));
    atomicAdd(&d_s1[d * 4 + h], ee);
}

// ---------- layer 1: pass 2 (normalize + aggregate + emit alpha), 8 thr/edge ----------
__global__ void k_edge1_agg(const int* __restrict__ ei, float* __restrict__ alpha_out,
                            int E, int ET) {
    int t = blockIdx.x * blockDim.x + threadIdx.x;
    int i = t >> 3;
    if (i >= ET) return;
    int j = t & 7;          // chunk 0..7
    int h = j >> 1;         // head 0..3
    int s, d; edge_sd(ei, i, E, s, d);

    float ee = __expf(lrelu(d_as1[s * 4 + h] + d_ad1[d * 4 + h]));
    float al = ee / (d_s1[d * 4 + h] + 1e-16f);

    if (alpha_out && (j & 1) == 0) alpha_out[i * 4 + h] = al;

    float4 v = ((const float4*)&d_h1[s * 32])[j];
    atomicAdd(&((float4*)&d_out1[d * 32])[j],
              make_float4(v.x * al, v.y * al, v.z * al, v.w * al));
}

// ---------- layer 2: node transform (elu + GEMV) + init, packed outputs ----------
__global__ void k_node2(const float* __restrict__ b1, const float* __restrict__ W2,
                        const float* __restrict__ asr, const float* __restrict__ adr, int N) {
    int n = blockIdx.x * blockDim.x + threadIdx.x;
    if (n >= N) return;
    float g0 = 0.f, g1 = 0.f;
#pragma unroll
    for (int k = 0; k < 32; k++) {
        float v = d_out1[n * 32 + k] + b1[k];
        v = v > 0.f ? v : expm1f(v);
        g0 += v * W2[k * 2];
        g1 += v * W2[k * 2 + 1];
    }
    d_p2s[n] = make_float4(g0, g1, g0 * asr[0] + g1 * asr[1], 0.f);
    d_p2d[n] = make_float2(g0 * adr[0] + g1 * adr[1], 0.f);
    d_out2[n * 2] = 0.f;
    d_out2[n * 2 + 1] = 0.f;
}

// ---------- layer 2: edge passes (packed gathers) ----------
__global__ void k_edge2_sum(const int* __restrict__ ei, int E, int ET) {
    int i = blockIdx.x * blockDim.x + threadIdx.x;
    if (i >= ET) return;
    int s, d; edge_sd(ei, i, E, s, d);
    float as2 = d_p2s[s].z;
    float ad2 = d_p2d[d].x;
    float ee = __expf(lrelu(as2 + ad2));
    atomicAdd(&((float*)d_p2d)[2 * d + 1], ee);   // accumulate s2 into p2d.y
}
__global__ void k_edge2_agg(const int* __restrict__ ei, float* __restrict__ alpha_out,
                            int E, int ET) {
    int i = blockIdx.x * blockDim.x + threadIdx.x;
    if (i >= ET) return;
    int s, d; edge_sd(ei, i, E, s, d);
    float4 ps = d_p2s[s];                 // {g0, g1, as2, ·}  one gather
    float2 pd = d_p2d[d];                 // {ad2, s2}         one gather
    float ee = __expf(lrelu(ps.z + pd.x));
    float al = ee / (pd.y + 1e-16f);
    if (alpha_out) alpha_out[i] = al;
    atomicAdd((float2*)&d_out2[d * 2], make_float2(ps.x * al, ps.y * al));
}

// ---------- finalize: out[0..2N) = out2 + b2 ; zero tail ----------
__global__ void k_finalize(float* __restrict__ out, const float* __restrict__ b2,
                           int N, int ET, int out_size) {
    int i = blockIdx.x * blockDim.x + threadIdx.x;
    if (i >= out_size) return;
    int total = N * 2 + ET * 4 + ET;
    if (i < N * 2) {
        out[i] = d_out2[i] + b2[i & 1];
    } else if (out_size >= total) {
        if (i >= total) out[i] = 0.f;   // tail beyond known layout
        // [2N, total): written by edge agg kernels (alpha1, alpha2)
    } else {
        out[i] = 0.f;                   // unknown smaller layout: deterministic fill
    }
}

extern "C" void kernel_launch(void* const* d_in, const int* in_sizes, int n_in,
                              void* d_out, int out_size) {
    const float* x   = (const float*)d_in[0];
    const int*   ei  = (const int*)d_in[1];   // edge_index stored as int32 by harness
    // d_in[2] = edge_attr (ignored by reference)
    const float* W1   = (const float*)d_in[3];
    const float* as1  = (const float*)d_in[4];
    const float* ad1  = (const float*)d_in[5];
    const float* b1   = (const float*)d_in[6];
    const float* W2   = (const float*)d_in[7];
    const float* as2  = (const float*)d_in[8];
    const float* ad2  = (const float*)d_in[9];
    const float* b2   = (const float*)d_in[10];
    float* out = (float*)d_out;

    int N  = in_sizes[0] / 2;
    int E  = in_sizes[1] / 2;
    int ET = E + N;
    long long total = (long long)N * 2 + (long long)ET * 5;

    float* alpha1_out = (out_size >= total) ? out + (size_t)N * 2 : nullptr;
    float* alpha2_out = (out_size >= total) ? out + (size_t)N * 2 + (size_t)ET * 4 : nullptr;

    const int T = 256;
    int gN   = (N  + T - 1) / T;
    int gET  = (ET + T - 1) / T;
    int gET4 = (ET * 4 + T - 1) / T;
    int gET8 = (ET * 8 + T - 1) / T;
    int gO   = (out_size + T - 1) / T;

    k_node1<<<gN, T>>>(x, W1, as1, ad1, N);
    k_edge1_sum<<<gET4, T>>>(ei, E, ET);
    k_edge1_agg<<<gET8, T>>>(ei, alpha1_out, E, ET);
    k_node2<<<gN, T>>>(b1, W2, as2, ad2, N);
    k_edge2_sum<<<gET, T>>>(ei, E, ET);
    k_edge2_agg<<<gET, T>>>(ei, alpha2_out, E, ET);
    k_finalize<<<gO, T>>>(out, b2, N, ET, out_size);
}